// round 3
// baseline (speedup 1.0000x reference)
#include <cuda_runtime.h>

// out[b,i,j,f] = x[b,i,f] * y[b,j,f]; second half of d_out = 0.75 * first half.
// x,y: [B,3,128] fp32. Mandatory traffic: 307MB read + 922MB write.
// Each thread handles TWO batch elements: 12 front-batched float4 loads,
// then 36 stores -> longer same-direction DRAM bursts (read/write turnaround).

__global__ __launch_bounds__(256)
void tp_kernel(const float4* __restrict__ x,
               const float4* __restrict__ y,
               float4* __restrict__ out,
               int B)
{
    int idx = blockIdx.x * blockDim.x + threadIdx.x;
    int half_total = (B / 2) * 32;       // thread-pairs: 2 b's each
    const size_t half = (size_t)B * 9 * 32;

    if (idx < half_total) {
        int bp = idx >> 5;               // pair index
        int f4 = idx & 31;
        int b0 = bp * 2;

        float4 xv[2][3], yv[2][3];
#pragma unroll
        for (int u = 0; u < 2; u++)
#pragma unroll
            for (int i = 0; i < 3; i++) {
                xv[u][i] = x[(size_t)((b0 + u) * 3 + i) * 32 + f4];
                yv[u][i] = y[(size_t)((b0 + u) * 3 + i) * 32 + f4];
            }

#pragma unroll
        for (int u = 0; u < 2; u++) {
            size_t base = ((size_t)(b0 + u) * 9) * 32 + f4;
#pragma unroll
            for (int i = 0; i < 3; i++)
#pragma unroll
                for (int j = 0; j < 3; j++) {
                    float4 p;
                    p.x = xv[u][i].x * yv[u][j].x;
                    p.y = xv[u][i].y * yv[u][j].y;
                    p.z = xv[u][i].z * yv[u][j].z;
                    p.w = xv[u][i].w * yv[u][j].w;
                    size_t o = base + (size_t)(i * 3 + j) * 32;
                    out[o] = p;
                    float4 q;
                    q.x = 0.75f * p.x;
                    q.y = 0.75f * p.y;
                    q.z = 0.75f * p.z;
                    q.w = 0.75f * p.w;
                    out[half + o] = q;
                }
        }
    }

    // Tail: if B is odd, last b handled by the first 32 threads of block 0
    if ((B & 1) && idx < 32) {
        int b = B - 1;
        int f4 = idx;
        float4 xv[3], yv[3];
#pragma unroll
        for (int i = 0; i < 3; i++) {
            xv[i] = x[(size_t)(b * 3 + i) * 32 + f4];
            yv[i] = y[(size_t)(b * 3 + i) * 32 + f4];
        }
#pragma unroll
        for (int i = 0; i < 3; i++)
#pragma unroll
            for (int j = 0; j < 3; j++) {
                float4 p;
                p.x = xv[i].x * yv[j].x;
                p.y = xv[i].y * yv[j].y;
                p.z = xv[i].z * yv[j].z;
                p.w = xv[i].w * yv[j].w;
                size_t o = ((size_t)b * 9 + i * 3 + j) * 32 + f4;
                out[o] = p;
                float4 q;
                q.x = 0.75f * p.x;
                q.y = 0.75f * p.y;
                q.z = 0.75f * p.z;
                q.w = 0.75f * p.w;
                out[half + o] = q;
            }
    }
}

extern "C" void kernel_launch(void* const* d_in, const int* in_sizes, int n_in,
                              void* d_out, int out_size)
{
    const float4* x = (const float4*)d_in[0];
    const float4* y = (const float4*)d_in[1];
    float4* out = (float4*)d_out;

    int B = in_sizes[0] / (3 * 128);     // 100000
    int total = (B / 2) * 32;
    int threads = 256;
    int blocks = (total + threads - 1) / threads;
    tp_kernel<<<blocks, threads>>>(x, y, out, B);
}